// round 15
// baseline (speedup 1.0000x reference)
#include <cuda_runtime.h>
#include <cuda_fp16.h>
#include <cstdint>
#include <cstddef>

// ---------------- problem constants ----------------
#define B_  64
#define T_  256
#define I_  1024
#define H_  4096
#define NC_ 16

// ---------------- GEMM tiling ----------------
#define BM 128
#define BN 128
#define BK 64
#define NKT (I_/BK)                 // 16 k-iterations
#define STAGES 3
#define A_STAGE_B (BM*BK*2)         // 16384 B
#define B_STAGE_B (BK*BN*2)         // 16384 B
#define STAGE_B   (A_STAGE_B + B_STAGE_B)   // 32768
#define SMEM_TOTAL (STAGES*STAGE_B) // 98304

// ---------------- fp16 scratch (device globals; allocation-free) ----------------
__device__ __align__(1024) __half g_xh[(size_t)B_ * T_ * I_];   // x rounded rn -> fp16
__device__ __align__(1024) __half g_wh[(size_t)NC_ * I_ * H_];  // W rounded rn -> fp16
__device__ int g_cat[B_];
__device__ int g_perm[B_];          // batches sorted by category

// ---------------- PTX helpers ----------------
__device__ __forceinline__ uint32_t smem_u32(const void* p) {
    uint32_t a;
    asm("{ .reg .u64 t; cvta.to.shared.u64 t, %1; cvt.u32.u64 %0, t; }" : "=r"(a) : "l"(p));
    return a;
}
__device__ __forceinline__ void cp_async16(uint32_t saddr, const void* gaddr) {
    asm volatile("cp.async.cg.shared.global [%0], [%1], 16;\n" :: "r"(saddr), "l"(gaddr));
}
__device__ __forceinline__ void cp_commit() {
    asm volatile("cp.async.commit_group;\n" ::: "memory");
}
template <int N>
__device__ __forceinline__ void cp_wait() {
    asm volatile("cp.async.wait_group %0;\n" :: "n"(N) : "memory");
}
__device__ __forceinline__ void ldsm_x4(uint32_t& r0, uint32_t& r1, uint32_t& r2, uint32_t& r3,
                                        uint32_t addr) {
    asm volatile("ldmatrix.sync.aligned.m8n8.x4.shared.b16 {%0,%1,%2,%3}, [%4];"
                 : "=r"(r0), "=r"(r1), "=r"(r2), "=r"(r3) : "r"(addr));
}
__device__ __forceinline__ void ldsm_x4_t(uint32_t& r0, uint32_t& r1, uint32_t& r2, uint32_t& r3,
                                          uint32_t addr) {
    asm volatile("ldmatrix.sync.aligned.m8n8.x4.trans.shared.b16 {%0,%1,%2,%3}, [%4];"
                 : "=r"(r0), "=r"(r1), "=r"(r2), "=r"(r3) : "r"(addr));
}
__device__ __forceinline__ void mma_fp16(float& c0, float& c1, float& c2, float& c3,
                                         uint32_t a0, uint32_t a1, uint32_t a2, uint32_t a3,
                                         uint32_t b0, uint32_t b1) {
    asm volatile(
        "mma.sync.aligned.m16n8k16.row.col.f32.f16.f16.f32 "
        "{%0,%1,%2,%3}, {%4,%5,%6,%7}, {%8,%9}, {%0,%1,%2,%3};\n"
        : "+f"(c0), "+f"(c1), "+f"(c2), "+f"(c3)
        : "r"(a0), "r"(a1), "r"(a2), "r"(a3), "r"(b0), "r"(b1));
}

// ---------------- prep: category decode + cat-sort (int32/int64 runtime detect) ----------------
__global__ void prep_cat_kernel(const void* __restrict__ cat_raw) {
    if (threadIdx.x != 0) return;
    const int* c32 = (const int*)cat_raw;
    bool is64 = true;
    for (int i = 1; i < 64; i += 2) is64 &= (c32[i] == 0);
    int cats[B_];
    for (int b = 0; b < B_; b++) {
        int c = is64 ? (int)((const long long*)cat_raw)[b] : c32[b];
        cats[b] = c;
        g_cat[b] = c;
    }
    int idx = 0;
    for (int c = 0; c < NC_; c++)
        for (int b = 0; b < B_; b++)
            if (cats[b] == c) g_perm[idx++] = b;
}

// ---------------- prep: fp32 -> fp16 (rn), x and W in one kernel ----------------
#define XN4 ((size_t)B_ * T_ * I_ / 4)
#define WN4 ((size_t)NC_ * I_ * H_ / 4)
__global__ void conv_kernel(const float4* __restrict__ x, const float4* __restrict__ W) {
    __half2* ox = (__half2*)g_xh;
    __half2* ow = (__half2*)g_wh;
    const size_t stride = (size_t)gridDim.x * blockDim.x;
    for (size_t i = (size_t)blockIdx.x * blockDim.x + threadIdx.x; i < XN4 + WN4; i += stride) {
        if (i < XN4) {
            float4 v = x[i];
            ox[2 * i + 0] = __floats2half2_rn(v.x, v.y);
            ox[2 * i + 1] = __floats2half2_rn(v.z, v.w);
        } else {
            size_t j = i - XN4;
            float4 v = W[j];
            ow[2 * j + 0] = __floats2half2_rn(v.x, v.y);
            ow[2 * j + 1] = __floats2half2_rn(v.z, v.w);
        }
    }
}

// ---------------- GEMM: fp16 mma.sync m16n8k16, ldmatrix, cp.async 3-stage ----------------
__global__ __launch_bounds__(256, 2)
void gemm_kernel(const float* __restrict__ bias, float* __restrict__ out) {
    extern __shared__ char smem[];
    const uint32_t sb = smem_u32(smem);

    const int tid  = threadIdx.x;
    const int lane = tid & 31;
    const int wrp  = tid >> 5;
    const int wm   = wrp >> 2;        // 0..1
    const int wn   = wrp & 3;        // 0..3

    const int bz = g_perm[blockIdx.z];          // cat-sorted batch schedule
    const int m0 = blockIdx.y * BM;
    const int n0 = blockIdx.x * BN;
    const int cat = g_cat[bz];

    const __half* xA = g_xh + (size_t)(bz * T_ + m0) * I_;
    const __half* WB = g_wh + (size_t)cat * I_ * H_ + n0;

    // cp.async tile loader: A 128r x 8c(16B), B 64r x 16c(16B); swizzle c ^= (row&7)
    auto load_tiles = [&](int kt, int s) {
        const uint32_t soA = sb + s * STAGE_B;
        const uint32_t soB = soA + A_STAGE_B;
        #pragma unroll
        for (int i = 0; i < 4; i++) {
            int id = tid + i * 256;
            int r = id >> 3, c = id & 7;
            uint32_t dst = soA + (uint32_t)(r * 128 + ((c ^ (r & 7)) << 4));
            cp_async16(dst, xA + (size_t)r * I_ + kt * BK + c * 8);
        }
        #pragma unroll
        for (int i = 0; i < 4; i++) {
            int id = tid + i * 256;
            int r = id >> 4, c = id & 15;
            uint32_t dst = soB + (uint32_t)(r * 256 + ((c ^ (r & 7)) << 4));
            cp_async16(dst, WB + (size_t)(kt * BK + r) * H_ + c * 8);
        }
    };

    // fragment address pieces
    uint32_t aRowBase[4], aRow7[4];
    #pragma unroll
    for (int tm = 0; tm < 4; tm++) {
        int r = wm * 64 + tm * 16 + (lane & 15);
        aRowBase[tm] = (uint32_t)(r * 128);
        aRow7[tm] = (uint32_t)(r & 7);
    }
    const uint32_t aHi = (uint32_t)(lane >> 4);
    const uint32_t bRowBase = (uint32_t)((lane & 15) * 256);
    uint32_t bChunkX[2];
    #pragma unroll
    for (int nh = 0; nh < 2; nh++)
        bChunkX[nh] = (uint32_t)(((wn * 4 + nh * 2 + (lane >> 4)) ^ (lane & 7)) << 4);

    float acc[4][4][4];
    #pragma unroll
    for (int a = 0; a < 4; a++)
        #pragma unroll
        for (int b = 0; b < 4; b++)
            #pragma unroll
            for (int c = 0; c < 4; c++) acc[a][b][c] = 0.0f;

    // prologue: stages 0 and 1 in flight
    load_tiles(0, 0); cp_commit();
    load_tiles(1, 1); cp_commit();

    for (int kt = 0; kt < NKT; ++kt) {
        const int cur = kt % STAGES;
        if (kt + 1 < NKT) cp_wait<1>(); else cp_wait<0>();
        __syncthreads();                    // single barrier per k-iter
        if (kt + 2 < NKT) {                 // issue 2 iterations ahead
            load_tiles(kt + 2, (kt + 2) % STAGES);
            cp_commit();
        }

        const uint32_t soA = sb + cur * STAGE_B;
        const uint32_t soB = soA + A_STAGE_B;

        #pragma unroll
        for (int kk = 0; kk < BK / 16; kk++) {
            uint32_t af[4][4];
            #pragma unroll
            for (int tm = 0; tm < 4; tm++) {
                uint32_t chunk = (uint32_t)(kk * 2) + aHi;
                uint32_t addr = soA + aRowBase[tm] + ((chunk ^ aRow7[tm]) << 4);
                ldsm_x4(af[tm][0], af[tm][1], af[tm][2], af[tm][3], addr);
            }
            uint32_t bf[2][4];
            #pragma unroll
            for (int nh = 0; nh < 2; nh++) {
                uint32_t addr = soB + (uint32_t)(kk * 16 * 256) + bRowBase + bChunkX[nh];
                ldsm_x4_t(bf[nh][0], bf[nh][1], bf[nh][2], bf[nh][3], addr);
            }
            #pragma unroll
            for (int tm = 0; tm < 4; tm++)
                #pragma unroll
                for (int tn = 0; tn < 4; tn++)
                    mma_fp16(acc[tm][tn][0], acc[tm][tn][1], acc[tm][tn][2], acc[tm][tn][3],
                             af[tm][0], af[tm][1], af[tm][2], af[tm][3],
                             bf[tn >> 1][(tn & 1) * 2], bf[tn >> 1][(tn & 1) * 2 + 1]);
        }
    }

    // ---- epilogue: add bias, fp32 stores ----
    const int g  = lane >> 2;
    const int tg = lane & 3;
    float* outp = out + (size_t)bz * T_ * H_;
    const float* bp = bias + (size_t)cat * H_;
    #pragma unroll
    for (int tm = 0; tm < 4; tm++) {
        int r = m0 + wm * 64 + tm * 16 + g;
        #pragma unroll
        for (int tn = 0; tn < 4; tn++) {
            int c = n0 + wn * 32 + tn * 8 + 2 * tg;
            float b0v = bp[c], b1v = bp[c + 1];
            float2 v0 = make_float2(acc[tm][tn][0] + b0v, acc[tm][tn][1] + b1v);
            float2 v1 = make_float2(acc[tm][tn][2] + b0v, acc[tm][tn][3] + b1v);
            *(float2*)&outp[(size_t)r * H_ + c]       = v0;
            *(float2*)&outp[(size_t)(r + 8) * H_ + c] = v1;
        }
    }
}

// ---------------- host ----------------
extern "C" void kernel_launch(void* const* d_in, const int* in_sizes, int n_in,
                              void* d_out, int out_size) {
    const float* x   = (const float*)d_in[0];
    const void*  cat = d_in[1];
    const float* W   = (const float*)d_in[2];
    const float* b   = (const float*)d_in[3];
    float* out = (float*)d_out;

    prep_cat_kernel<<<1, 32>>>(cat);
    conv_kernel<<<2960, 256>>>((const float4*)x, (const float4*)W);

    cudaFuncSetAttribute(gemm_kernel, cudaFuncAttributeMaxDynamicSharedMemorySize,
                         SMEM_TOTAL);
    dim3 grid(H_ / BN, T_ / BM, B_);   // (32, 2, 64)
    gemm_kernel<<<grid, 256, SMEM_TOTAL>>>(b, out);
}